// round 17
// baseline (speedup 1.0000x reference)
#include <cuda_runtime.h>
#include <cstdint>

// Problem dims
#define BATCH 16
#define NN    2048
#define EE    2048
#define FF    256

// Scratch layout (floats):
//   xtoE  : 8M   @ 0
//   EtoX  : 8M   @ 8388608
//   neT   : 8M   @ 16777216   (tf32, [b][f][node])
//   newET : 8M   @ 25165824   (tf32, [b][f][e])
//   WneT  : 64K  @ 33554432   (tf32, [f][k], k=256)
//   WeT   : 128K @ 33619968   (tf32, [f][k], k=512)
//   WnT   : 128K @ 33751040   (tf32, [f][k], k=512)
__device__ float g_scratch[33882112];

// ---------------------------------------------------------------------------
#define STR 36   // smem row stride (floats); 36 ≡ 4 mod 32 -> conflict-free

__device__ __forceinline__ float tf32r(float x) {
    unsigned u;
    asm("cvt.rna.tf32.f32 %0, %1;" : "=r"(u) : "f"(x));
    return __uint_as_float(u);
}

__device__ __forceinline__ void ldsm4(uint32_t* d, uint32_t addr) {
    asm volatile("ldmatrix.sync.aligned.m8n8.x4.shared.b16 {%0,%1,%2,%3}, [%4];"
                 : "=r"(d[0]), "=r"(d[1]), "=r"(d[2]), "=r"(d[3]) : "r"(addr));
}

__device__ __forceinline__ void mma_tf32(float* c, const uint32_t* a, const uint32_t* b) {
    asm volatile(
        "mma.sync.aligned.m16n8k8.row.col.f32.tf32.tf32.f32 "
        "{%0,%1,%2,%3}, {%4,%5,%6,%7}, {%8,%9}, {%0,%1,%2,%3};\n"
        : "+f"(c[0]), "+f"(c[1]), "+f"(c[2]), "+f"(c[3])
        : "r"(a[0]), "r"(a[1]), "r"(a[2]), "r"(a[3]), "r"(b[0]), "r"(b[1]));
}

__device__ __forceinline__ void cp_async16(uint32_t smem_addr, const void* gptr) {
    asm volatile("cp.async.cg.shared.global [%0], [%1], 16;"
                 :: "r"(smem_addr), "l"(gptr) : "memory");
}
__device__ __forceinline__ void cp_commit() {
    asm volatile("cp.async.commit_group;" ::: "memory");
}
__device__ __forceinline__ void cp_wait_all() {
    asm volatile("cp.async.wait_group 0;" ::: "memory");
}

__device__ __forceinline__ uint32_t offA_lane(int lane) {
    return (uint32_t)(((lane & 15) * STR + (lane >> 4) * 4) * 4);
}
__device__ __forceinline__ uint32_t offB_lane(int lane) {
    return (uint32_t)((((lane >> 4) * 8 + (lane & 7)) * STR + ((lane >> 3) & 1) * 4) * 4);
}

// ---------------------------------------------------------------------------
// Weight prep: WT[f][k] = tf32(W[k][f])  (one tiny launch)
// ---------------------------------------------------------------------------
__global__ void prep_weights(const float* __restrict__ Wne, const float* __restrict__ We,
                             const float* __restrict__ Wn, float* __restrict__ WneT,
                             float* __restrict__ WeT, float* __restrict__ WnT) {
    int idx = blockIdx.x * 256 + threadIdx.x;
    if (idx < 65536) {
        int f = idx >> 8, k = idx & 255;
        WneT[f * 256 + k] = tf32r(Wne[k * 256 + f]);
        return;
    }
    idx -= 65536;
    if (idx < 131072) {
        int f = idx >> 9, k = idx & 511;
        WeT[f * 512 + k] = tf32r(We[k * 256 + f]);
        return;
    }
    idx -= 131072;
    int f = idx >> 9, k = idx & 511;
    WnT[f * 512 + k] = tf32r(Wn[k * 256 + f]);
}

// ===========================================================================
// Big GEMM on H (per batch: A = H[b] 2048x2048, BT tf32 [256][2048], C 2048x256)
// CTA tile 128 x 256 x Ktile=32; 512 threads, 16 warps 4x4, 32x64 per warp.
// A staged via regs (cvt + fused norm-sum); B staged via cp.async (already tf32).
// TRANSA=1: C[m][f] = scale_m * sum_k A[k][m] BT[f][k]   (x_to_E; 1/colsum)
// TRANSA=0: C[m][f] = scale_m * sum_k A[m][k] BT[f][k]   (E_to_x; 1/rowsum)
// ===========================================================================
#define BASZ (128 * STR)   // 4608 floats
#define BBSZ (256 * STR)   // 9216 floats

template <int TRANSA>
__global__ __launch_bounds__(512, 1)
void gemm_big_tc(const float* __restrict__ Hbase, const float* __restrict__ BTmat,
                 float* __restrict__ Cmat) {
    extern __shared__ float sm[];
    float* Abuf = sm;                  // [2][BASZ]
    __shared__ float red[1024];

    int b  = blockIdx.y;
    int m0 = blockIdx.x * 128;
    const float* A  = Hbase + (size_t)b * NN * EE;
    const float* BT = BTmat + (size_t)b * FF * 2048;   // [f][k] tf32
    float*       Cp = Cmat  + (size_t)b * 2048 * FF;

    int tid = threadIdx.x, warp = tid >> 5, lane = tid & 31;
    int wm = warp >> 2, wn = warp & 3;   // 4x4 warp grid, 32x64 per warp
    int g = lane >> 2, t = lane & 3;

    uint32_t su   = (uint32_t)__cvta_generic_to_shared(sm);
    uint32_t offA = offA_lane(lane);
    uint32_t offB = offB_lane(lane);

    int mloc  = tid & 127;     // owned m column (TRANSA=1 staging)
    int khalf = tid >> 7;      // 0..3

    float acc[2][8][4];
    #pragma unroll
    for (int i = 0; i < 2; ++i)
        #pragma unroll
        for (int j = 0; j < 8; ++j)
            #pragma unroll
            for (int r = 0; r < 4; ++r) acc[i][j][r] = 0.f;

    float4 Ar[2];
    float  hsum[2] = {0.f, 0.f};

    // A: LDG into regs; B: cp.async straight into smem (pre-converted tf32)
    auto load_tile = [&](int k0, int buf) {
        #pragma unroll
        for (int r = 0; r < 2; ++r) {
            if (TRANSA) {
                int kg = khalf * 2 + r;   // float4 group within 32-k
                const float* p = &A[(size_t)(k0 + 4 * kg) * EE + m0 + mloc];
                Ar[r].x = p[0]; Ar[r].y = p[EE]; Ar[r].z = p[2 * EE]; Ar[r].w = p[3 * EE];
            } else {
                int ma = r * 64 + (tid >> 3);
                Ar[r] = *reinterpret_cast<const float4*>(
                    &A[(size_t)(m0 + ma) * EE + k0 + ((tid & 7) << 2)]);
            }
        }
        uint32_t bB = su + (uint32_t)(2 * BASZ + buf * BBSZ) * 4;
        #pragma unroll
        for (int r = 0; r < 4; ++r) {
            int row = r * 64 + (tid >> 3);
            cp_async16(bB + (uint32_t)(row * STR + ((tid & 7) << 2)) * 4,
                       &BT[(size_t)row * 2048 + k0 + ((tid & 7) << 2)]);
        }
        cp_commit();
    };

    auto store_A = [&](int buf) {
        float* Ad = Abuf + buf * BASZ;
        #pragma unroll
        for (int r = 0; r < 2; ++r) {
            if (TRANSA) hsum[0] += Ar[r].x + Ar[r].y + Ar[r].z + Ar[r].w;
            else        hsum[r] += Ar[r].x + Ar[r].y + Ar[r].z + Ar[r].w;
            float4 w;
            w.x = tf32r(Ar[r].x); w.y = tf32r(Ar[r].y);
            w.z = tf32r(Ar[r].z); w.w = tf32r(Ar[r].w);
            if (TRANSA) {
                int kg = khalf * 2 + r;
                *reinterpret_cast<float4*>(&Ad[mloc * STR + 4 * kg]) = w;
            } else {
                int ma = r * 64 + (tid >> 3);
                *reinterpret_cast<float4*>(&Ad[ma * STR + ((tid & 7) << 2)]) = w;
            }
        }
    };

    auto compute_part = [&](int buf, int s0, int s1) {
        uint32_t aB = su + (uint32_t)(buf * BASZ) * 4;
        uint32_t bB = su + (uint32_t)(2 * BASZ + buf * BBSZ) * 4;
        #pragma unroll
        for (int ks = s0; ks < s1; ++ks) {
            uint32_t kkb = ks * 8 * 4;
            uint32_t a[2][4], bb[4][4];
            #pragma unroll
            for (int p = 0; p < 4; ++p)
                ldsm4(bb[p], bB + (uint32_t)((wn * 64 + p * 16) * STR * 4) + kkb + offB);
            #pragma unroll
            for (int mt = 0; mt < 2; ++mt)
                ldsm4(a[mt], aB + (uint32_t)((wm * 32 + mt * 16) * STR * 4) + kkb + offA);
            #pragma unroll
            for (int mt = 0; mt < 2; ++mt)
                #pragma unroll
                for (int nt = 0; nt < 8; ++nt)
                    mma_tf32(acc[mt][nt], a[mt], &bb[nt >> 1][(nt & 1) * 2]);
        }
    };

    const int T = 2048 / 32;
    load_tile(0, 0);
    store_A(0);
    cp_wait_all();
    __syncthreads();
    int buf = 0;
    #pragma unroll 1
    for (int it = 0; it < T; ++it) {
        if (it + 1 < T) load_tile((it + 1) * 32, buf ^ 1);
        compute_part(buf, 0, 3);
        if (it + 1 < T) store_A(buf ^ 1);
        compute_part(buf, 3, 4);
        if (it + 1 < T) { cp_wait_all(); __syncthreads(); buf ^= 1; }
    }

    // Reduce norm sums -> red[0..127] = inv scale per local m
    __syncthreads();
    if (TRANSA) {
        red[khalf * 128 + mloc] = hsum[0];
        __syncthreads();
        if (tid < 128) {
            float s = red[tid] + red[128 + tid] + red[256 + tid] + red[384 + tid];
            red[tid] = (s > 0.f) ? (1.f / s) : 0.f;
        }
    } else {
        #pragma unroll
        for (int r = 0; r < 2; ++r)
            red[(tid & 7) * 128 + r * 64 + (tid >> 3)] = hsum[r];
        __syncthreads();
        if (tid < 128) {
            float s = 0.f;
            #pragma unroll
            for (int w = 0; w < 8; ++w) s += red[w * 128 + tid];
            red[tid] = (s > 0.f) ? (1.f / s) : 0.f;
        }
    }
    __syncthreads();

    // Epilogue: per-output-row safe-norm scaling
    #pragma unroll
    for (int mt = 0; mt < 2; ++mt) {
        int ml = wm * 32 + mt * 16 + g;
        int m  = m0 + ml;
        float sc0 = red[ml];
        float sc1 = red[ml + 8];
        #pragma unroll
        for (int nt = 0; nt < 8; ++nt) {
            int n = wn * 64 + nt * 8 + 2 * t;
            float2 v0 = make_float2(acc[mt][nt][0] * sc0, acc[mt][nt][1] * sc0);
            float2 v1 = make_float2(acc[mt][nt][2] * sc1, acc[mt][nt][3] * sc1);
            *reinterpret_cast<float2*>(&Cp[(size_t)m * FF + n]) = v0;
            *reinterpret_cast<float2*>(&Cp[(size_t)(m + 8) * FF + n]) = v1;
        }
    }
}

// ===========================================================================
// Fused small GEMM (R16 known-good, unchanged): relu([A1|A2] @ W + bias);
// W pre-transposed tf32 [f][KTOT]. TOUT=0: f32 out; 1: transposed tf32 out;
// 2: both.
// ===========================================================================
#define ASZ (128 * STR)
#define BSZ (128 * STR)

template <int KTOT, int TOUT>
__global__ __launch_bounds__(256, 2)
void gemm_fused_tc(const float* __restrict__ A1, const float* __restrict__ A2,
                   const float* __restrict__ WT, const float* __restrict__ bias,
                   float* __restrict__ Cn, float* __restrict__ Ct) {
    extern __shared__ float sm[];
    float* Abuf = sm;
    float* Bbuf = sm + 2 * ASZ;

    int m0 = blockIdx.y * 128, n0 = blockIdx.x * 128;
    int tid = threadIdx.x, warp = tid >> 5, lane = tid & 31;
    int wm = warp >> 2, wn = warp & 3;
    int g = lane >> 2, t = lane & 3;

    uint32_t su   = (uint32_t)__cvta_generic_to_shared(sm);
    uint32_t offA = offA_lane(lane);
    uint32_t offB = offB_lane(lane);

    float acc[4][4][4];
    #pragma unroll
    for (int i = 0; i < 4; ++i)
        #pragma unroll
        for (int j = 0; j < 4; ++j)
            #pragma unroll
            for (int r = 0; r < 4; ++r) acc[i][j][r] = 0.f;

    float4 Ar[4], Br[4];

    auto load_tile = [&](int k0) {
        const float* Asrc = (KTOT == 256 || k0 < 256) ? A1 : A2;
        int kloc = (KTOT == 256 || k0 < 256) ? k0 : (k0 - 256);
        #pragma unroll
        for (int r = 0; r < 4; ++r) {
            int ma = r * 32 + (tid >> 3), ca = (tid & 7) << 2;
            Ar[r] = *reinterpret_cast<const float4*>(&Asrc[(size_t)(m0 + ma) * FF + kloc + ca]);
            Br[r] = *reinterpret_cast<const float4*>(&WT[(size_t)(n0 + ma) * KTOT + k0 + ca]);
        }
    };

    auto store_tile = [&](int buf) {
        float* Ad = Abuf + buf * ASZ;
        float* Bd = Bbuf + buf * BSZ;
        #pragma unroll
        for (int r = 0; r < 4; ++r) {
            float4 w;
            w.x = tf32r(Ar[r].x); w.y = tf32r(Ar[r].y);
            w.z = tf32r(Ar[r].z); w.w = tf32r(Ar[r].w);
            int ma = r * 32 + (tid >> 3), ca = (tid & 7) << 2;
            *reinterpret_cast<float4*>(&Ad[ma * STR + ca]) = w;
            *reinterpret_cast<float4*>(&Bd[ma * STR + ca]) = Br[r];
        }
    };

    auto compute_part = [&](int buf, int s0, int s1) {
        uint32_t aB = su + (buf * ASZ) * 4;
        uint32_t bB = su + (2 * ASZ + buf * BSZ) * 4;
        #pragma unroll
        for (int ks = s0; ks < s1; ++ks) {
            uint32_t kkb = ks * 8 * 4;
            uint32_t a[4][4], bb[2][4];
            #pragma unroll
            for (int p = 0; p < 2; ++p)
                ldsm4(bb[p], bB + (uint32_t)((wn * 32 + p * 16) * STR * 4) + kkb + offB);
            #pragma unroll
            for (int mt = 0; mt < 4; ++mt)
                ldsm4(a[mt], aB + (uint32_t)((wm * 64 + mt * 16) * STR * 4) + kkb + offA);
            #pragma unroll
            for (int mt = 0; mt < 4; ++mt) {
                mma_tf32(acc[mt][0], a[mt], &bb[0][0]);
                mma_tf32(acc[mt][1], a[mt], &bb[0][2]);
                mma_tf32(acc[mt][2], a[mt], &bb[1][0]);
                mma_tf32(acc[mt][3], a[mt], &bb[1][2]);
            }
        }
    };

    const int T = KTOT / 32;
    load_tile(0);
    store_tile(0);
    __syncthreads();
    int buf = 0;
    #pragma unroll 1
    for (int it = 0; it < T; ++it) {
        if (it + 1 < T) load_tile((it + 1) * 32);
        compute_part(buf, 0, 3);
        if (it + 1 < T) store_tile(buf ^ 1);
        compute_part(buf, 3, 4);
        if (it + 1 < T) { __syncthreads(); buf ^= 1; }
    }

    // Epilogue: bias + relu (+ optional transposed tf32 write)
    #pragma unroll
    for (int nt = 0; nt < 4; ++nt) {
        int n = n0 + wn * 32 + nt * 8 + 2 * t;
        float bv0 = bias[n], bv1 = bias[n + 1];
        #pragma unroll
        for (int mt = 0; mt < 4; ++mt) {
            int m = m0 + wm * 64 + mt * 16 + g;
            float2 v0 = make_float2(fmaxf(acc[mt][nt][0] + bv0, 0.f),
                                    fmaxf(acc[mt][nt][1] + bv1, 0.f));
            float2 v1 = make_float2(fmaxf(acc[mt][nt][2] + bv0, 0.f),
                                    fmaxf(acc[mt][nt][3] + bv1, 0.f));
            if (TOUT != 1) {
                *reinterpret_cast<float2*>(&Cn[(size_t)m * FF + n]) = v0;
                *reinterpret_cast<float2*>(&Cn[(size_t)(m + 8) * FF + n]) = v1;
            }
            if (TOUT != 0) {
                int batch = m >> 11, node = m & 2047;
                float* Tb = Ct + (size_t)batch * FF * 2048;
                Tb[(size_t)n * 2048 + node]             = tf32r(v0.x);
                Tb[(size_t)(n + 1) * 2048 + node]       = tf32r(v0.y);
                Tb[(size_t)n * 2048 + node + 8]         = tf32r(v1.x);
                Tb[(size_t)(n + 1) * 2048 + node + 8]   = tf32r(v1.y);
            }
        }
    }
}

// ---------------------------------------------------------------------------
extern "C" void kernel_launch(void* const* d_in, const int* in_sizes, int n_in,
                              void* d_out, int out_size) {
    const float* H    = (const float*)d_in[0];
    const float* E    = (const float*)d_in[1];
    const float* x    = (const float*)d_in[2];
    const float* W_ne = (const float*)d_in[3];
    const float* b_ne = (const float*)d_in[4];
    const float* W_e  = (const float*)d_in[5];
    const float* b_e  = (const float*)d_in[6];
    const float* W_n  = (const float*)d_in[7];
    const float* b_n  = (const float*)d_in[8];

    float* out  = (float*)d_out;
    float* newE = out;
    float* newx = out + (size_t)BATCH * EE * FF;

    float* scratch = nullptr;
    cudaGetSymbolAddress((void**)&scratch, g_scratch);
    float* xtoE  = scratch;
    float* EtoX  = scratch + 8388608;
    float* neT   = scratch + 16777216;
    float* newET = scratch + 25165824;
    float* WneT  = scratch + 33554432;
    float* WeT   = scratch + 33619968;
    float* WnT   = scratch + 33751040;

    const int SMEM_BIG   = (2 * BASZ + 2 * BBSZ) * 4;   // 110592
    const int SMEM_FUSED = (2 * ASZ + 2 * BSZ) * 4;     // 73728

    static bool attr_done = false;
    if (!attr_done) {
        cudaFuncSetAttribute(gemm_big_tc<1>, cudaFuncAttributeMaxDynamicSharedMemorySize, SMEM_BIG);
        cudaFuncSetAttribute(gemm_big_tc<0>, cudaFuncAttributeMaxDynamicSharedMemorySize, SMEM_BIG);
        cudaFuncSetAttribute(gemm_fused_tc<256, 1>, cudaFuncAttributeMaxDynamicSharedMemorySize, SMEM_FUSED);
        cudaFuncSetAttribute(gemm_fused_tc<512, 2>, cudaFuncAttributeMaxDynamicSharedMemorySize, SMEM_FUSED);
        cudaFuncSetAttribute(gemm_fused_tc<512, 0>, cudaFuncAttributeMaxDynamicSharedMemorySize, SMEM_FUSED);
        attr_done = true;
    }

    // 0) transpose + tf32-convert weights
    prep_weights<<<1280, 256>>>(W_ne, W_e, W_n, WneT, WeT, WnT);

    // 1) neT = tf32(relu(x @ W_ne + b_ne))^T
    gemm_fused_tc<256, 1><<<dim3(FF / 128, BATCH * NN / 128), 256, SMEM_FUSED>>>(
        x, nullptr, WneT, b_ne, nullptr, neT);

    // 2) x_to_E = colscale * (H^T @ ne)   [colsum fused in-kernel]
    gemm_big_tc<1><<<dim3(EE / 128, BATCH), 512, SMEM_BIG>>>(H, neT, xtoE);

    // 3) new_E = relu([x_to_E, E] @ W_e + b_e)  (+ transposed tf32 copy)
    gemm_fused_tc<512, 2><<<dim3(FF / 128, BATCH * EE / 128), 256, SMEM_FUSED>>>(
        xtoE, E, WeT, b_e, newE, newET);

    // 4) E_to_x = rowscale * (H @ new_E)  [rowsum fused in-kernel]
    gemm_big_tc<0><<<dim3(NN / 128, BATCH), 512, SMEM_BIG>>>(H, newET, EtoX);

    // 5) new_x = relu([E_to_x, x] @ W_n + b_n)
    gemm_fused_tc<512, 0><<<dim3(FF / 128, BATCH * NN / 128), 256, SMEM_FUSED>>>(
        EtoX, x, WnT, b_n, newx, nullptr);
}